// round 10
// baseline (speedup 1.0000x reference)
#include <cuda_runtime.h>
#include <cstdint>

#define NT      512
#define PIX     16384
#define NB      64
#define NSAMP   1024
#define NV      778
#define NPAIR   389      // NV/2
#define SLOTS   32
#define NVB     (NB * NV)
#define DIST_GRID 768    // 512 A-blocks + 256 B-blocks

typedef unsigned long long ull;

// ---------------- device scratch (no allocations allowed) ----------------
__device__ uint32_t g_hist[NB * 4096];           // per-batch bucket counts
__device__ uint32_t g_bl[NB * 4096 * SLOTS];     // bucket entry lists (32 MB)
__device__ float4   g_samp[NB * NSAMP];          // xyz + 0.5*|s|^2
__device__ uint32_t g_vminb[NVB];                // bits of d2min (>=0), atomicMin
__device__ ull      g_sacc;                      // fixed-point sum of sample mins
__device__ uint32_t g_done;                      // k_dist completion counter

// ---------------- tf32 round-to-nearest-even (cuBLAS operand rounding) ----
__device__ __forceinline__ float tf32r(float x) {
    uint32_t u = __float_as_uint(x);
    uint32_t r = (u + 0xFFFu + ((u >> 13) & 1u)) & ~0x1FFFu;
    return __uint_as_float(r);
}

// ---------------- packed f32x2 helpers ----------------
__device__ __forceinline__ ull pk2(float lo, float hi) {
    ull r;
    asm("mov.b64 %0, {%1, %2};" : "=l"(r) : "f"(lo), "f"(hi));
    return r;
}

__device__ __forceinline__ float2 dot3p(ull nx, ull X, ull ny, ull Y,
                                        ull nz, ull Z, ull W) {
    float lo, hi;
    asm("{\n\t"
        ".reg .b64 t;\n\t"
        "fma.rn.f32x2 t, %2, %3, %4;\n\t"
        "fma.rn.f32x2 t, %5, %6, t;\n\t"
        "fma.rn.f32x2 t, %7, %8, t;\n\t"
        "mov.b64 {%0, %1}, t;\n\t"
        "}"
        : "=f"(lo), "=f"(hi)
        : "l"(nz), "l"(Z), "l"(W), "l"(ny), "l"(Y), "l"(nx), "l"(X));
    return make_float2(lo, hi);
}

// ------- threefry2x32-20, JAX partitionable counter-mode, key = (0,1) -----
__device__ __forceinline__ uint32_t rotl32(uint32_t x, uint32_t d) {
    return (x << d) | (x >> (32u - d));
}

__device__ __forceinline__ uint32_t threefry_bits_part(uint32_t e) {
    uint32_t x0 = 0u;
    uint32_t x1 = e;
    const uint32_t k0 = 0u, k1 = 1u;
    const uint32_t k2 = 0x1BD11BDAu ^ k0 ^ k1;
    x0 += k0; x1 += k1;
#define TF_RND(r) { x0 += x1; x1 = rotl32(x1, r) ^ x0; }
    TF_RND(13u) TF_RND(15u) TF_RND(26u) TF_RND(6u)
    x0 += k1; x1 += k2 + 1u;
    TF_RND(17u) TF_RND(29u) TF_RND(16u) TF_RND(24u)
    x0 += k2; x1 += k0 + 2u;
    TF_RND(13u) TF_RND(15u) TF_RND(26u) TF_RND(6u)
    x0 += k0; x1 += k1 + 3u;
    TF_RND(17u) TF_RND(29u) TF_RND(16u) TF_RND(24u)
    x0 += k1; x1 += k2 + 4u;
    TF_RND(13u) TF_RND(15u) TF_RND(26u) TF_RND(6u)
    x0 += k2; x1 += k0 + 5u;
#undef TF_RND
    return x0 ^ x1;
}

// ---------------- pixel -> normalized xyz (+ 0.5*|s|^2) ----------------
__device__ __forceinline__ float4 pix_xyz4(int p, float imgval, const float* sp) {
    float tj = 2.0f * (float)(p & 127) / 127.0f - 1.0f;
    float ti = 2.0f * (float)(p >> 7)  / 127.0f - 1.0f;
    float u = (tj + 1.0f) * 64.0f;
    float v = (ti + 1.0f) * 64.0f;
    float d = imgval * sp[11] + sp[8];
    float ut = tf32r(u), vt = tf32r(v);
    float uw = fmaf(sp[0], ut, fmaf(sp[1], vt, sp[2]));
    float vw = fmaf(sp[3], ut, fmaf(sp[4], vt, sp[5]));
    float x = (uw - 320.0f) * d / 588.03f;
    float y = (vw - 240.0f) * d / 587.07f;   // FLIP = 1
    float xn = (x - sp[6]) / sp[9];
    float yn = (y - sp[7]) / sp[10];
    float zn = (d - sp[8]) / sp[11];
    float hs = 0.5f * (xn * xn + yn * yn + zn * zn);
    return make_float4(xn, yn, zn, hs);
}

// ================= K0: zero histograms + init mins + counters ==========
__global__ void __launch_bounds__(NT)
k_zero() {
    int i = blockIdx.x * NT + threadIdx.x;
    if (i < NB * 4096) g_hist[i] = 0u;
    else if (i < NB * 4096 + NVB) g_vminb[i - NB * 4096] = 0x7F800000u;
    if (i == 0) { g_sacc = 0ull; g_done = 0u; }
}

// ===== KA: full-chip threefry + bucket binning (grid 1024) =====
__global__ void __launch_bounds__(256)
kA(const float* __restrict__ real) {
    int gt = blockIdx.x * 256 + threadIdx.x;   // 0..262143
#pragma unroll
    for (int k = 0; k < 4; k++) {
        uint32_t e = (uint32_t)gt + (uint32_t)k * 262144u;  // 0..2^20-1
        uint32_t bits = threefry_bits_part(e);
        bool valid = real[e] <= 0.99f;
        if (valid) {
            uint32_t sk = bits >> 9;             // 23-bit key
            uint32_t bucket = sk >> 11;          // top 12 bits
            uint32_t low11  = sk & 0x7FFu;
            uint32_t bi = (e >> 14) * 4096u + bucket;
            uint32_t pos = atomicAdd(&g_hist[bi], 1u);
            if (pos < SLOTS)
                g_bl[bi * SLOTS + pos] = (low11 << 14) | (e & 16383u);
        }
    }
}

// ===== KC: per-batch threshold + scan-based emit (grid 64) =====
__global__ void __launch_bounds__(NT)
kC(const float* __restrict__ real, const float* __restrict__ center,
   const float* __restrict__ Mmat, const float* __restrict__ cube) {
    __shared__ uint32_t hist[4096];
    __shared__ uint32_t wsum[16];
    __shared__ uint32_t woff[17];
    __shared__ float    s_par[12];
    __shared__ uint32_t s_T, s_need;

    int b = blockIdx.x;
    int tid = threadIdx.x;
    int lane = tid & 31;
    int wid = tid >> 5;

    if (tid == 0) {
        const float* Mb = Mmat + b * 9;
        double a00 = Mb[0], a01 = Mb[1], a02 = Mb[2];
        double a10 = Mb[3], a11 = Mb[4], a12 = Mb[5];
        double a20 = Mb[6], a21 = Mb[7], a22 = Mb[8];
        double det = a00 * (a11 * a22 - a12 * a21)
                   - a01 * (a10 * a22 - a12 * a20)
                   + a02 * (a10 * a21 - a11 * a20);
        double inv = 1.0 / det;
        s_par[0] = tf32r((float)( (a11 * a22 - a12 * a21) * inv));
        s_par[1] = tf32r((float)(-(a01 * a22 - a02 * a21) * inv));
        s_par[2] = tf32r((float)( (a01 * a12 - a02 * a11) * inv));
        s_par[3] = tf32r((float)(-(a10 * a22 - a12 * a20) * inv));
        s_par[4] = tf32r((float)( (a00 * a22 - a02 * a20) * inv));
        s_par[5] = tf32r((float)(-(a00 * a12 - a02 * a10) * inv));
        s_par[6] = center[b * 3 + 0];
        s_par[7] = center[b * 3 + 1];
        s_par[8] = center[b * 3 + 2];
        s_par[9]  = cube[b * 3 + 0] * 0.5f;
        s_par[10] = cube[b * 3 + 1] * 0.5f;
        s_par[11] = cube[b * 3 + 2] * 0.5f;
    }
    for (int i = tid; i < 4096; i += NT) hist[i] = g_hist[b * 4096 + i];
    __syncthreads();

    // ---- threshold via shfl prefix over 512 per-thread sums (contiguous) --
    {
        uint32_t c = 0;
#pragma unroll
        for (int k = 0; k < 8; k++) c += hist[tid * 8 + k];
        uint32_t p = c;
#pragma unroll
        for (int d = 1; d < 32; d <<= 1) {
            uint32_t n = __shfl_up_sync(0xFFFFFFFFu, p, d);
            if (lane >= d) p += n;
        }
        if (lane == 31) wsum[wid] = p;
        __syncthreads();
        if (wid == 0) {
            uint32_t w = (lane < 16) ? wsum[lane] : 0u;
            uint32_t q = w;
#pragma unroll
            for (int d = 1; d < 16; d <<= 1) {
                uint32_t n = __shfl_up_sync(0xFFFFFFFFu, q, d);
                if (lane >= d) q += n;
            }
            if (lane < 16) woff[lane] = q - w;
            if (lane == 15) woff[16] = q;
        }
        __syncthreads();
        uint32_t Pincl = p + woff[wid];
        uint32_t above = woff[16] - Pincl;
        uint32_t S = above + c;
        const uint32_t target = NSAMP;
        if (above < target && S >= target) {
            uint32_t cgt = above;
            for (int k = 7; k >= 0; k--) {
                uint32_t h = hist[tid * 8 + k];
                if (cgt + h >= target) {
                    s_T = (uint32_t)(tid * 8 + k);
                    s_need = target - cgt;
                    break;
                }
                cgt += h;
            }
        }
        __syncthreads();
    }
    uint32_t T = s_T;
    uint32_t need = s_need;

    const float* img = real + b * PIX;
    float4* out = g_samp + b * NSAMP;

    // ---- deterministic scan-based emit, interleaved bucket ownership ----
    uint32_t nk[8];
    uint32_t cnt = 0;
#pragma unroll
    for (int k = 0; k < 8; k++) {
        uint32_t bucket = (uint32_t)(k * NT + tid);
        uint32_t n = 0;
        if (bucket > T) {
            n = hist[bucket];
            if (n > SLOTS) n = SLOTS;
        }
        nk[k] = n;
        cnt += n;
    }
    {
        uint32_t p = cnt;
#pragma unroll
        for (int d = 1; d < 32; d <<= 1) {
            uint32_t n = __shfl_up_sync(0xFFFFFFFFu, p, d);
            if (lane >= d) p += n;
        }
        if (lane == 31) wsum[wid] = p;
        __syncthreads();
        if (wid == 0) {
            uint32_t w = (lane < 16) ? wsum[lane] : 0u;
            uint32_t q = w;
#pragma unroll
            for (int d = 1; d < 16; d <<= 1) {
                uint32_t n = __shfl_up_sync(0xFFFFFFFFu, q, d);
                if (lane >= d) q += n;
            }
            if (lane < 16) woff[lane] = q - w;
        }
        __syncthreads();
        uint32_t off = (p - cnt) + woff[wid];    // exclusive global offset
#pragma unroll
        for (int k = 0; k < 8; k++) {
            uint32_t n = nk[k];
            if (n) {
                uint32_t bucket = (uint32_t)(k * NT + tid);
                const uint32_t* bl = g_bl + (uint32_t)(b * 4096 + bucket) * SLOTS;
                for (uint32_t j = 0; j < n; j++) {
                    uint32_t e = bl[j];
                    uint32_t pp = e & 16383u;
                    out[off++] = pix_xyz4((int)pp, img[pp], s_par);
                }
            }
        }
    }

    // boundary bucket: sort desc by key, asc by index; take `need`
    if (tid == 0) {
        uint32_t n = hist[T];
        if (n > SLOTS) n = SLOTS;
        uint32_t arr[SLOTS];
        const uint32_t* bl = g_bl + (uint32_t)(b * 4096 + T) * SLOTS;
        for (uint32_t i = 0; i < n; i++) arr[i] = bl[i];
        for (uint32_t i = 1; i < n; i++) {
            uint32_t e = arr[i];
            int j = (int)i - 1;
            while (j >= 0) {
                uint32_t f = arr[j];
                bool before = ((e >> 14) > (f >> 14)) ||
                              ((e >> 14) == (f >> 14) && (e & 16383u) < (f & 16383u));
                if (before) { arr[j + 1] = f; j--; } else break;
            }
            arr[j + 1] = e;
        }
        uint32_t start = NSAMP - need;
        for (uint32_t i = 0; i < need && i < n; i++) {
            uint32_t pp = arr[i] & 16383u;
            out[start + i] = pix_xyz4((int)pp, img[pp], s_par);
        }
    }
}

// ===== K_DIST: blocks 0..511 vert pass (A); 512..767 sample pass (B);
//               last finished block does the final reduction =====
__global__ void __launch_bounds__(256)
k_dist(const float* __restrict__ verts, float* __restrict__ outp) {
    __shared__ ull   shbuf[4 * NPAIR];   // A: 4x64 packed samples; B: packed verts
    __shared__ float pm[256];
    __shared__ bool  isLast;

    int tid = threadIdx.x;

    if (blockIdx.x < 512) {
        // -------- A: per-vert min over a 128-sample chunk --------
        int blk = blockIdx.x;
        int b = blk >> 3;
        int chunk = blk & 7;
        ull* px = shbuf;         // 64 each
        ull* py = shbuf + 64;
        ull* pz = shbuf + 128;
        ull* pw = shbuf + 192;

        const float4* sp = g_samp + b * NSAMP + chunk * 128;
        if (tid < 64) {
            float4 f0 = sp[2 * tid];
            float4 f1 = sp[2 * tid + 1];
            px[tid] = pk2(f0.x, f1.x);
            py[tid] = pk2(f0.y, f1.y);
            pz[tid] = pk2(f0.z, f1.z);
            pw[tid] = pk2(f0.w, f1.w);
        }
        __syncthreads();

        if (tid < 195) {
            const float* vb = verts + b * NV * 3;
            ull nx[4], ny[4], nz[4];
            float hw[4];
            int vidx[4];
#pragma unroll
            for (int k = 0; k < 4; k++) {
                int v = 4 * tid + k;
                vidx[k] = v < NV ? v : NV - 1;
                float x = vb[3 * vidx[k]], y = vb[3 * vidx[k] + 1], z = vb[3 * vidx[k] + 2];
                nx[k] = pk2(-x, -x);
                ny[k] = pk2(-y, -y);
                nz[k] = pk2(-z, -z);
                hw[k] = 0.5f * (x * x + y * y + z * z);
            }
            float ml[4] = {1e30f, 1e30f, 1e30f, 1e30f};
            float mh[4] = {1e30f, 1e30f, 1e30f, 1e30f};
#pragma unroll 4
            for (int i = 0; i < 64; i++) {
                ull X = px[i], Y = py[i], Z = pz[i], W = pw[i];
#pragma unroll
                for (int k = 0; k < 4; k++) {
                    float2 d = dot3p(nx[k], X, ny[k], Y, nz[k], Z, W);
                    ml[k] = fminf(ml[k], d.x);
                    mh[k] = fminf(mh[k], d.y);
                }
            }
#pragma unroll
            for (int k = 0; k < 4; k++) {
                if (4 * tid + k < NV) {
                    float val = 2.0f * (fminf(ml[k], mh[k]) + hw[k]);  // >= 0
                    atomicMin(&g_vminb[b * NV + vidx[k]], __float_as_uint(val));
                }
            }
        }
    } else {
        // -------- B: per-sample min over ALL verts, 1 sample/thread --------
        int blk = blockIdx.x - 512;
        int b = blk >> 2;
        int chunk = blk & 3;
        ull* vx = shbuf;               // NPAIR each
        ull* vy = shbuf + NPAIR;
        ull* vz = shbuf + 2 * NPAIR;
        ull* vw = shbuf + 3 * NPAIR;

        const float* vb = verts + b * NV * 3;
        for (int j = tid; j < NPAIR; j += 256) {
            float ax = vb[6 * j],     ay = vb[6 * j + 1], az = vb[6 * j + 2];
            float bx = vb[6 * j + 3], by = vb[6 * j + 4], bz = vb[6 * j + 5];
            vx[j] = pk2(ax, bx);
            vy[j] = pk2(ay, by);
            vz[j] = pk2(az, bz);
            vw[j] = pk2(0.5f * (ax * ax + ay * ay + az * az),
                        0.5f * (bx * bx + by * by + bz * bz));
        }
        float4 me = g_samp[b * NSAMP + chunk * 256 + tid];
        __syncthreads();

        ull ax = pk2(-me.x, -me.x), ay = pk2(-me.y, -me.y), az = pk2(-me.z, -me.z);
        float ma = 1e30f, mb = 1e30f;
#pragma unroll 4
        for (int j = 0; j < NPAIR; j++) {
            float2 d = dot3p(ax, vx[j], ay, vy[j], az, vz[j], vw[j]);
            ma = fminf(ma, d.x);
            mb = fminf(mb, d.y);
        }
        float sum = 2.0f * (fminf(ma, mb) + me.w);

        pm[tid] = sum;
        __syncthreads();
        for (int off = 128; off > 0; off >>= 1) {
            if (tid < off) pm[tid] += pm[tid + off];
            __syncthreads();
        }
        if (tid == 0) {
            // deterministic fixed-point accumulation (integer add commutes)
            double v = (double)pm[0];
            if (v < 0.0) v = 0.0;
            ull fx = (ull)(v * 4294967296.0);
            atomicAdd(&g_sacc, fx);
        }
    }

    // -------- completion counter; last block reduces --------
    __syncthreads();
    if (tid == 0) {
        __threadfence();
        uint32_t t = atomicAdd(&g_done, 1u);
        isLast = (t == DIST_GRID - 1);
    }
    __syncthreads();
    if (isLast) {
        __threadfence();
        float acc = 0.0f;
        for (int i = tid; i < NVB; i += 256)
            acc += __uint_as_float(g_vminb[i]);
        pm[tid] = acc;
        __syncthreads();
        for (int off = 128; off > 0; off >>= 1) {
            if (tid < off) pm[tid] += pm[tid + off];
            __syncthreads();
        }
        if (tid == 0) {
            double s = (double)g_sacc * (1.0 / 4294967296.0);
            outp[0] = (float)(s / (double)(NB * NSAMP)) +
                      pm[0] / (float)(NB * NV);
        }
    }
}

// ======================== launch ========================
extern "C" void kernel_launch(void* const* d_in, const int* in_sizes, int n_in,
                              void* d_out, int out_size) {
    const float* real   = (const float*)d_in[0];
    // d_in[1] synth unused, d_in[3] faces unused
    const float* verts  = (const float*)d_in[2];
    const float* center = (const float*)d_in[4];
    const float* Mmat   = (const float*)d_in[5];
    const float* cube   = (const float*)d_in[6];

    int nz = NB * 4096 + NVB;
    k_zero<<<(nz + NT - 1) / NT, NT>>>();
    kA<<<1024, 256>>>(real);
    kC<<<NB, NT>>>(real, center, Mmat, cube);
    k_dist<<<DIST_GRID, 256>>>(verts, (float*)d_out);
}

// round 11
// speedup vs baseline: 1.0319x; 1.0319x over previous
#include <cuda_runtime.h>
#include <cstdint>

#define NT      512
#define PIX     16384
#define NB      64
#define NSAMP   1024
#define NV      778
#define NPAIR   389      // NV/2
#define SLOTS   32
#define NVB     (NB * NV)

typedef unsigned long long ull;

// ---------------- device scratch (no allocations allowed) ----------------
// NOTE: zero-initialized at module load; kernels restore invariants each run:
//   g_hist: zeroed by kC after consumption (kA precondition)
//   g_vminb: set to +inf by kC (k_dist precondition)
//   g_sacc: reset by k_red after consumption
__device__ uint32_t g_hist[NB * 4096];           // per-batch bucket counts
__device__ uint32_t g_bl[NB * 4096 * SLOTS];     // bucket entry lists (32 MB)
__device__ float4   g_samp[NB * NSAMP];          // xyz + 0.5*|s|^2
__device__ uint32_t g_vminb[NVB];                // bits of d2min (>=0), atomicMin
__device__ ull      g_sacc;                      // fixed-point sum of sample mins

// ---------------- tf32 round-to-nearest-even (cuBLAS operand rounding) ----
__device__ __forceinline__ float tf32r(float x) {
    uint32_t u = __float_as_uint(x);
    uint32_t r = (u + 0xFFFu + ((u >> 13) & 1u)) & ~0x1FFFu;
    return __uint_as_float(r);
}

// ---------------- packed f32x2 helpers ----------------
__device__ __forceinline__ ull pk2(float lo, float hi) {
    ull r;
    asm("mov.b64 %0, {%1, %2};" : "=l"(r) : "f"(lo), "f"(hi));
    return r;
}

__device__ __forceinline__ float2 dot3p(ull nx, ull X, ull ny, ull Y,
                                        ull nz, ull Z, ull W) {
    float lo, hi;
    asm("{\n\t"
        ".reg .b64 t;\n\t"
        "fma.rn.f32x2 t, %2, %3, %4;\n\t"
        "fma.rn.f32x2 t, %5, %6, t;\n\t"
        "fma.rn.f32x2 t, %7, %8, t;\n\t"
        "mov.b64 {%0, %1}, t;\n\t"
        "}"
        : "=f"(lo), "=f"(hi)
        : "l"(nz), "l"(Z), "l"(W), "l"(ny), "l"(Y), "l"(nx), "l"(X));
    return make_float2(lo, hi);
}

// ------- threefry2x32-20, JAX partitionable counter-mode, key = (0,1) -----
__device__ __forceinline__ uint32_t rotl32(uint32_t x, uint32_t d) {
    return (x << d) | (x >> (32u - d));
}

__device__ __forceinline__ uint32_t threefry_bits_part(uint32_t e) {
    uint32_t x0 = 0u;
    uint32_t x1 = e;
    const uint32_t k0 = 0u, k1 = 1u;
    const uint32_t k2 = 0x1BD11BDAu ^ k0 ^ k1;
    x0 += k0; x1 += k1;
#define TF_RND(r) { x0 += x1; x1 = rotl32(x1, r) ^ x0; }
    TF_RND(13u) TF_RND(15u) TF_RND(26u) TF_RND(6u)
    x0 += k1; x1 += k2 + 1u;
    TF_RND(17u) TF_RND(29u) TF_RND(16u) TF_RND(24u)
    x0 += k2; x1 += k0 + 2u;
    TF_RND(13u) TF_RND(15u) TF_RND(26u) TF_RND(6u)
    x0 += k0; x1 += k1 + 3u;
    TF_RND(17u) TF_RND(29u) TF_RND(16u) TF_RND(24u)
    x0 += k1; x1 += k2 + 4u;
    TF_RND(13u) TF_RND(15u) TF_RND(26u) TF_RND(6u)
    x0 += k2; x1 += k0 + 5u;
#undef TF_RND
    return x0 ^ x1;
}

// ---------------- pixel -> normalized xyz (+ 0.5*|s|^2) ----------------
__device__ __forceinline__ float4 pix_xyz4(int p, float imgval, const float* sp) {
    float tj = 2.0f * (float)(p & 127) / 127.0f - 1.0f;
    float ti = 2.0f * (float)(p >> 7)  / 127.0f - 1.0f;
    float u = (tj + 1.0f) * 64.0f;
    float v = (ti + 1.0f) * 64.0f;
    float d = imgval * sp[11] + sp[8];
    float ut = tf32r(u), vt = tf32r(v);
    float uw = fmaf(sp[0], ut, fmaf(sp[1], vt, sp[2]));
    float vw = fmaf(sp[3], ut, fmaf(sp[4], vt, sp[5]));
    float x = (uw - 320.0f) * d / 588.03f;
    float y = (vw - 240.0f) * d / 587.07f;   // FLIP = 1
    float xn = (x - sp[6]) / sp[9];
    float yn = (y - sp[7]) / sp[10];
    float zn = (d - sp[8]) / sp[11];
    float hs = 0.5f * (xn * xn + yn * yn + zn * zn);
    return make_float4(xn, yn, zn, hs);
}

// ===== KA: full-chip threefry + bucket binning (grid 1024) =====
// precondition: g_hist == 0 (module load, then kC re-zeroes every run)
__global__ void __launch_bounds__(256)
kA(const float* __restrict__ real) {
    int gt = blockIdx.x * 256 + threadIdx.x;   // 0..262143
#pragma unroll
    for (int k = 0; k < 4; k++) {
        uint32_t e = (uint32_t)gt + (uint32_t)k * 262144u;  // 0..2^20-1
        uint32_t bits = threefry_bits_part(e);
        bool valid = real[e] <= 0.99f;
        if (valid) {
            uint32_t sk = bits >> 9;             // 23-bit key
            uint32_t bucket = sk >> 11;          // top 12 bits
            uint32_t low11  = sk & 0x7FFu;
            uint32_t bi = (e >> 14) * 4096u + bucket;
            uint32_t pos = atomicAdd(&g_hist[bi], 1u);
            if (pos < SLOTS)
                g_bl[bi * SLOTS + pos] = (low11 << 14) | (e & 16383u);
        }
    }
}

// ===== KC: per-batch threshold + scan-based emit (grid 64) =====
// also: re-zeroes g_hist slice, inits g_vminb to +inf
__global__ void __launch_bounds__(NT)
kC(const float* __restrict__ real, const float* __restrict__ center,
   const float* __restrict__ Mmat, const float* __restrict__ cube) {
    __shared__ uint32_t hist[4096];
    __shared__ uint32_t wsum[16];
    __shared__ uint32_t woff[17];
    __shared__ float    s_par[12];
    __shared__ uint32_t s_T, s_need;

    int b = blockIdx.x;
    int tid = threadIdx.x;
    int lane = tid & 31;
    int wid = tid >> 5;

    if (tid == 0) {
        const float* Mb = Mmat + b * 9;
        double a00 = Mb[0], a01 = Mb[1], a02 = Mb[2];
        double a10 = Mb[3], a11 = Mb[4], a12 = Mb[5];
        double a20 = Mb[6], a21 = Mb[7], a22 = Mb[8];
        double det = a00 * (a11 * a22 - a12 * a21)
                   - a01 * (a10 * a22 - a12 * a20)
                   + a02 * (a10 * a21 - a11 * a20);
        double inv = 1.0 / det;
        s_par[0] = tf32r((float)( (a11 * a22 - a12 * a21) * inv));
        s_par[1] = tf32r((float)(-(a01 * a22 - a02 * a21) * inv));
        s_par[2] = tf32r((float)( (a01 * a12 - a02 * a11) * inv));
        s_par[3] = tf32r((float)(-(a10 * a22 - a12 * a20) * inv));
        s_par[4] = tf32r((float)( (a00 * a22 - a02 * a20) * inv));
        s_par[5] = tf32r((float)(-(a00 * a12 - a02 * a10) * inv));
        s_par[6] = center[b * 3 + 0];
        s_par[7] = center[b * 3 + 1];
        s_par[8] = center[b * 3 + 2];
        s_par[9]  = cube[b * 3 + 0] * 0.5f;
        s_par[10] = cube[b * 3 + 1] * 0.5f;
        s_par[11] = cube[b * 3 + 2] * 0.5f;
    }
    for (int i = tid; i < 4096; i += NT) {
        hist[i] = g_hist[b * 4096 + i];
        g_hist[b * 4096 + i] = 0u;               // restore kA precondition
    }
    // init vert-min array for k_dist (full range, split across 64 CTAs)
    for (int i = b * NT + tid; i < NVB; i += NB * NT)
        g_vminb[i] = 0x7F800000u;
    __syncthreads();

    // ---- threshold via shfl prefix over 512 per-thread sums (contiguous) --
    {
        uint32_t c = 0;
#pragma unroll
        for (int k = 0; k < 8; k++) c += hist[tid * 8 + k];
        uint32_t p = c;
#pragma unroll
        for (int d = 1; d < 32; d <<= 1) {
            uint32_t n = __shfl_up_sync(0xFFFFFFFFu, p, d);
            if (lane >= d) p += n;
        }
        if (lane == 31) wsum[wid] = p;
        __syncthreads();
        if (wid == 0) {
            uint32_t w = (lane < 16) ? wsum[lane] : 0u;
            uint32_t q = w;
#pragma unroll
            for (int d = 1; d < 16; d <<= 1) {
                uint32_t n = __shfl_up_sync(0xFFFFFFFFu, q, d);
                if (lane >= d) q += n;
            }
            if (lane < 16) woff[lane] = q - w;
            if (lane == 15) woff[16] = q;
        }
        __syncthreads();
        uint32_t Pincl = p + woff[wid];
        uint32_t above = woff[16] - Pincl;
        uint32_t S = above + c;
        const uint32_t target = NSAMP;
        if (above < target && S >= target) {
            uint32_t cgt = above;
            for (int k = 7; k >= 0; k--) {
                uint32_t h = hist[tid * 8 + k];
                if (cgt + h >= target) {
                    s_T = (uint32_t)(tid * 8 + k);
                    s_need = target - cgt;
                    break;
                }
                cgt += h;
            }
        }
        __syncthreads();
    }
    uint32_t T = s_T;
    uint32_t need = s_need;

    const float* img = real + b * PIX;
    float4* out = g_samp + b * NSAMP;

    // ---- deterministic scan-based emit, interleaved bucket ownership ----
    uint32_t nk[8];
    uint32_t cnt = 0;
#pragma unroll
    for (int k = 0; k < 8; k++) {
        uint32_t bucket = (uint32_t)(k * NT + tid);
        uint32_t n = 0;
        if (bucket > T) {
            n = hist[bucket];
            if (n > SLOTS) n = SLOTS;
        }
        nk[k] = n;
        cnt += n;
    }
    {
        uint32_t p = cnt;
#pragma unroll
        for (int d = 1; d < 32; d <<= 1) {
            uint32_t n = __shfl_up_sync(0xFFFFFFFFu, p, d);
            if (lane >= d) p += n;
        }
        if (lane == 31) wsum[wid] = p;
        __syncthreads();
        if (wid == 0) {
            uint32_t w = (lane < 16) ? wsum[lane] : 0u;
            uint32_t q = w;
#pragma unroll
            for (int d = 1; d < 16; d <<= 1) {
                uint32_t n = __shfl_up_sync(0xFFFFFFFFu, q, d);
                if (lane >= d) q += n;
            }
            if (lane < 16) woff[lane] = q - w;
        }
        __syncthreads();
        uint32_t off = (p - cnt) + woff[wid];    // exclusive global offset
#pragma unroll
        for (int k = 0; k < 8; k++) {
            uint32_t n = nk[k];
            if (n) {
                uint32_t bucket = (uint32_t)(k * NT + tid);
                const uint32_t* bl = g_bl + (uint32_t)(b * 4096 + bucket) * SLOTS;
                for (uint32_t j = 0; j < n; j++) {
                    uint32_t e = bl[j];
                    uint32_t pp = e & 16383u;
                    out[off++] = pix_xyz4((int)pp, img[pp], s_par);
                }
            }
        }
    }

    // boundary bucket: sort desc by key, asc by index; take `need`
    if (tid == 0) {
        uint32_t n = hist[T];
        if (n > SLOTS) n = SLOTS;
        uint32_t arr[SLOTS];
        const uint32_t* bl = g_bl + (uint32_t)(b * 4096 + T) * SLOTS;
        for (uint32_t i = 0; i < n; i++) arr[i] = bl[i];
        for (uint32_t i = 1; i < n; i++) {
            uint32_t e = arr[i];
            int j = (int)i - 1;
            while (j >= 0) {
                uint32_t f = arr[j];
                bool before = ((e >> 14) > (f >> 14)) ||
                              ((e >> 14) == (f >> 14) && (e & 16383u) < (f & 16383u));
                if (before) { arr[j + 1] = f; j--; } else break;
            }
            arr[j + 1] = e;
        }
        uint32_t start = NSAMP - need;
        for (uint32_t i = 0; i < need && i < n; i++) {
            uint32_t pp = arr[i] & 16383u;
            out[start + i] = pix_xyz4((int)pp, img[pp], s_par);
        }
    }
}

// ===== K_DIST: blocks 0..255 vert pass (A); 256..383 sample pass (B) =====
// (reverted to the best-measured R9 configuration: 28.2us)
__global__ void __launch_bounds__(256)
k_dist(const float* __restrict__ verts) {
    __shared__ ull   shbuf[4 * NPAIR];   // A: 4x128 packed samples; B: packed verts
    __shared__ float pm[256];

    int tid = threadIdx.x;

    if (blockIdx.x < 256) {
        // -------- A: per-vert min over a 256-sample chunk --------
        int blk = blockIdx.x;
        int b = blk >> 2;
        int chunk = blk & 3;
        ull* px = shbuf;         // 128
        ull* py = shbuf + 128;
        ull* pz = shbuf + 256;
        ull* pw = shbuf + 384;

        const float4* sp = g_samp + b * NSAMP + chunk * 256;
        if (tid < 128) {
            float4 f0 = sp[2 * tid];
            float4 f1 = sp[2 * tid + 1];
            px[tid] = pk2(f0.x, f1.x);
            py[tid] = pk2(f0.y, f1.y);
            pz[tid] = pk2(f0.z, f1.z);
            pw[tid] = pk2(f0.w, f1.w);
        }
        __syncthreads();

        if (tid < 195) {
            const float* vb = verts + b * NV * 3;
            ull nx[4], ny[4], nz[4];
            float hw[4];
            int vidx[4];
#pragma unroll
            for (int k = 0; k < 4; k++) {
                int v = 4 * tid + k;
                vidx[k] = v < NV ? v : NV - 1;
                float x = vb[3 * vidx[k]], y = vb[3 * vidx[k] + 1], z = vb[3 * vidx[k] + 2];
                nx[k] = pk2(-x, -x);
                ny[k] = pk2(-y, -y);
                nz[k] = pk2(-z, -z);
                hw[k] = 0.5f * (x * x + y * y + z * z);
            }
            float ml[4] = {1e30f, 1e30f, 1e30f, 1e30f};
            float mh[4] = {1e30f, 1e30f, 1e30f, 1e30f};
#pragma unroll 4
            for (int i = 0; i < 128; i++) {
                ull X = px[i], Y = py[i], Z = pz[i], W = pw[i];
#pragma unroll
                for (int k = 0; k < 4; k++) {
                    float2 d = dot3p(nx[k], X, ny[k], Y, nz[k], Z, W);
                    ml[k] = fminf(ml[k], d.x);
                    mh[k] = fminf(mh[k], d.y);
                }
            }
#pragma unroll
            for (int k = 0; k < 4; k++) {
                if (4 * tid + k < NV) {
                    float val = 2.0f * (fminf(ml[k], mh[k]) + hw[k]);  // >= 0
                    atomicMin(&g_vminb[b * NV + vidx[k]], __float_as_uint(val));
                }
            }
        }
    } else {
        // -------- B: per-sample min over ALL verts, 2 samples/thread --------
        int blk = blockIdx.x - 256;
        int b = blk >> 1;
        int half = blk & 1;
        ull* vx = shbuf;               // NPAIR each
        ull* vy = shbuf + NPAIR;
        ull* vz = shbuf + 2 * NPAIR;
        ull* vw = shbuf + 3 * NPAIR;

        const float* vb = verts + b * NV * 3;
        for (int j = tid; j < NPAIR; j += 256) {
            float ax = vb[6 * j],     ay = vb[6 * j + 1], az = vb[6 * j + 2];
            float bx = vb[6 * j + 3], by = vb[6 * j + 4], bz = vb[6 * j + 5];
            vx[j] = pk2(ax, bx);
            vy[j] = pk2(ay, by);
            vz[j] = pk2(az, bz);
            vw[j] = pk2(0.5f * (ax * ax + ay * ay + az * az),
                        0.5f * (bx * bx + by * by + bz * bz));
        }
        int s0 = half * 512 + tid;
        int s1 = half * 512 + 256 + tid;
        float4 me0 = g_samp[b * NSAMP + s0];
        float4 me1 = g_samp[b * NSAMP + s1];
        __syncthreads();

        ull ax0 = pk2(-me0.x, -me0.x), ay0 = pk2(-me0.y, -me0.y), az0 = pk2(-me0.z, -me0.z);
        ull ax1 = pk2(-me1.x, -me1.x), ay1 = pk2(-me1.y, -me1.y), az1 = pk2(-me1.z, -me1.z);
        float m0a = 1e30f, m0b = 1e30f, m1a = 1e30f, m1b = 1e30f;
#pragma unroll 4
        for (int j = 0; j < NPAIR; j++) {
            ull X = vx[j], Y = vy[j], Z = vz[j], W = vw[j];
            float2 d0 = dot3p(ax0, X, ay0, Y, az0, Z, W);
            float2 d1 = dot3p(ax1, X, ay1, Y, az1, Z, W);
            m0a = fminf(m0a, d0.x); m0b = fminf(m0b, d0.y);
            m1a = fminf(m1a, d1.x); m1b = fminf(m1b, d1.y);
        }
        float sum = 2.0f * (fminf(m0a, m0b) + me0.w)
                  + 2.0f * (fminf(m1a, m1b) + me1.w);

        pm[tid] = sum;
        __syncthreads();
        for (int off = 128; off > 0; off >>= 1) {
            if (tid < off) pm[tid] += pm[tid + off];
            __syncthreads();
        }
        if (tid == 0) {
            // deterministic fixed-point accumulation (integer add commutes)
            double v = (double)pm[0];
            if (v < 0.0) v = 0.0;
            ull fx = (ull)(v * 4294967296.0);
            atomicAdd(&g_sacc, fx);
        }
    }
}

// ===== K_RED: final scalar (grid 1); resets g_sacc for next replay =====
__global__ void __launch_bounds__(NT)
k_red(float* __restrict__ out) {
    __shared__ float sred[NT];
    int tid = threadIdx.x;

    float acc = 0.0f;
    for (int i = tid; i < NVB; i += NT)
        acc += __uint_as_float(g_vminb[i]);
    sred[tid] = acc;
    __syncthreads();
    for (int off = NT / 2; off > 0; off >>= 1) {
        if (tid < off) sred[tid] += sred[tid + off];
        __syncthreads();
    }
    if (tid == 0) {
        double s = (double)g_sacc * (1.0 / 4294967296.0);
        g_sacc = 0ull;                     // restore for next replay
        out[0] = (float)(s / (double)(NB * NSAMP)) +
                 sred[0] / (float)(NB * NV);
    }
}

// ======================== launch ========================
extern "C" void kernel_launch(void* const* d_in, const int* in_sizes, int n_in,
                              void* d_out, int out_size) {
    const float* real   = (const float*)d_in[0];
    // d_in[1] synth unused, d_in[3] faces unused
    const float* verts  = (const float*)d_in[2];
    const float* center = (const float*)d_in[4];
    const float* Mmat   = (const float*)d_in[5];
    const float* cube   = (const float*)d_in[6];

    kA<<<1024, 256>>>(real);
    kC<<<NB, NT>>>(real, center, Mmat, cube);
    k_dist<<<384, 256>>>(verts);
    k_red<<<1, NT>>>((float*)d_out);
}

// round 12
// speedup vs baseline: 1.0993x; 1.0653x over previous
#include <cuda_runtime.h>
#include <cstdint>

#define NT      512
#define PIX     16384
#define NB      64
#define NSAMP   1024
#define NV      778
#define NPAIR   389      // NV/2
#define SLOTS   32
#define NVB     (NB * NV)
#define DGRID   384      // 256 A-blocks + 128 B-blocks

typedef unsigned long long ull;

// ---------------- device scratch (no allocations allowed) ----------------
// Zero-initialized at load; invariants restored every run:
//   g_hist zeroed by kC; g_vminb set +inf by kC; g_sacc/g_vacc/g_adone/g_done
//   reset by the tail blocks of k_dist.
__device__ uint32_t g_hist[NB * 4096];           // per-batch bucket counts
__device__ uint32_t g_bl[NB * 4096 * SLOTS];     // bucket entry lists (32 MB)
__device__ float4   g_samp[NB * NSAMP];          // xyz + 0.5*|s|^2
__device__ uint32_t g_vminb[NVB];                // bits of d2min (>=0), atomicMin
__device__ ull      g_sacc;                      // fixed-point sum of sample mins
__device__ ull      g_vacc;                      // fixed-point sum of vert mins
__device__ uint32_t g_adone[NB];                 // per-batch A-block counters
__device__ uint32_t g_done;                      // global completion counter

// ---------------- tf32 round-to-nearest-even (cuBLAS operand rounding) ----
__device__ __forceinline__ float tf32r(float x) {
    uint32_t u = __float_as_uint(x);
    uint32_t r = (u + 0xFFFu + ((u >> 13) & 1u)) & ~0x1FFFu;
    return __uint_as_float(r);
}

// ---------------- packed f32x2 helpers ----------------
__device__ __forceinline__ ull pk2(float lo, float hi) {
    ull r;
    asm("mov.b64 %0, {%1, %2};" : "=l"(r) : "f"(lo), "f"(hi));
    return r;
}

__device__ __forceinline__ float2 dot3p(ull nx, ull X, ull ny, ull Y,
                                        ull nz, ull Z, ull W) {
    float lo, hi;
    asm("{\n\t"
        ".reg .b64 t;\n\t"
        "fma.rn.f32x2 t, %2, %3, %4;\n\t"
        "fma.rn.f32x2 t, %5, %6, t;\n\t"
        "fma.rn.f32x2 t, %7, %8, t;\n\t"
        "mov.b64 {%0, %1}, t;\n\t"
        "}"
        : "=f"(lo), "=f"(hi)
        : "l"(nz), "l"(Z), "l"(W), "l"(ny), "l"(Y), "l"(nx), "l"(X));
    return make_float2(lo, hi);
}

// ------- threefry2x32-20, JAX partitionable counter-mode, key = (0,1) -----
__device__ __forceinline__ uint32_t rotl32(uint32_t x, uint32_t d) {
    return (x << d) | (x >> (32u - d));
}

__device__ __forceinline__ uint32_t threefry_bits_part(uint32_t e) {
    uint32_t x0 = 0u;
    uint32_t x1 = e;
    const uint32_t k0 = 0u, k1 = 1u;
    const uint32_t k2 = 0x1BD11BDAu ^ k0 ^ k1;
    x0 += k0; x1 += k1;
#define TF_RND(r) { x0 += x1; x1 = rotl32(x1, r) ^ x0; }
    TF_RND(13u) TF_RND(15u) TF_RND(26u) TF_RND(6u)
    x0 += k1; x1 += k2 + 1u;
    TF_RND(17u) TF_RND(29u) TF_RND(16u) TF_RND(24u)
    x0 += k2; x1 += k0 + 2u;
    TF_RND(13u) TF_RND(15u) TF_RND(26u) TF_RND(6u)
    x0 += k0; x1 += k1 + 3u;
    TF_RND(17u) TF_RND(29u) TF_RND(16u) TF_RND(24u)
    x0 += k1; x1 += k2 + 4u;
    TF_RND(13u) TF_RND(15u) TF_RND(26u) TF_RND(6u)
    x0 += k2; x1 += k0 + 5u;
#undef TF_RND
    return x0 ^ x1;
}

// ---------------- pixel -> normalized xyz (+ 0.5*|s|^2) ----------------
__device__ __forceinline__ float4 pix_xyz4(int p, float imgval, const float* sp) {
    float tj = 2.0f * (float)(p & 127) / 127.0f - 1.0f;
    float ti = 2.0f * (float)(p >> 7)  / 127.0f - 1.0f;
    float u = (tj + 1.0f) * 64.0f;
    float v = (ti + 1.0f) * 64.0f;
    float d = imgval * sp[11] + sp[8];
    float ut = tf32r(u), vt = tf32r(v);
    float uw = fmaf(sp[0], ut, fmaf(sp[1], vt, sp[2]));
    float vw = fmaf(sp[3], ut, fmaf(sp[4], vt, sp[5]));
    float x = (uw - 320.0f) * d / 588.03f;
    float y = (vw - 240.0f) * d / 587.07f;   // FLIP = 1
    float xn = (x - sp[6]) / sp[9];
    float yn = (y - sp[7]) / sp[10];
    float zn = (d - sp[8]) / sp[11];
    float hs = 0.5f * (xn * xn + yn * yn + zn * zn);
    return make_float4(xn, yn, zn, hs);
}

// ===== KA: full-chip threefry + bucket binning (grid 1024) =====
__global__ void __launch_bounds__(256)
kA(const float* __restrict__ real) {
    int gt = blockIdx.x * 256 + threadIdx.x;   // 0..262143
#pragma unroll
    for (int k = 0; k < 4; k++) {
        uint32_t e = (uint32_t)gt + (uint32_t)k * 262144u;  // 0..2^20-1
        uint32_t bits = threefry_bits_part(e);
        bool valid = real[e] <= 0.99f;
        if (valid) {
            uint32_t sk = bits >> 9;             // 23-bit key
            uint32_t bucket = sk >> 11;          // top 12 bits
            uint32_t low11  = sk & 0x7FFu;
            uint32_t bi = (e >> 14) * 4096u + bucket;
            uint32_t pos = atomicAdd(&g_hist[bi], 1u);
            if (pos < SLOTS)
                g_bl[bi * SLOTS + pos] = (low11 << 14) | (e & 16383u);
        }
    }
}

// ===== KC: per-batch threshold + scan-based emit (grid 64) =====
// also: re-zeroes g_hist slice, inits g_vminb to +inf
__global__ void __launch_bounds__(NT)
kC(const float* __restrict__ real, const float* __restrict__ center,
   const float* __restrict__ Mmat, const float* __restrict__ cube) {
    __shared__ uint32_t hist[4096];
    __shared__ uint32_t wsum[16];
    __shared__ uint32_t woff[17];
    __shared__ float    s_par[12];
    __shared__ uint32_t s_T, s_need;

    int b = blockIdx.x;
    int tid = threadIdx.x;
    int lane = tid & 31;
    int wid = tid >> 5;

    if (tid == 0) {
        const float* Mb = Mmat + b * 9;
        double a00 = Mb[0], a01 = Mb[1], a02 = Mb[2];
        double a10 = Mb[3], a11 = Mb[4], a12 = Mb[5];
        double a20 = Mb[6], a21 = Mb[7], a22 = Mb[8];
        double det = a00 * (a11 * a22 - a12 * a21)
                   - a01 * (a10 * a22 - a12 * a20)
                   + a02 * (a10 * a21 - a11 * a20);
        double inv = 1.0 / det;
        s_par[0] = tf32r((float)( (a11 * a22 - a12 * a21) * inv));
        s_par[1] = tf32r((float)(-(a01 * a22 - a02 * a21) * inv));
        s_par[2] = tf32r((float)( (a01 * a12 - a02 * a11) * inv));
        s_par[3] = tf32r((float)(-(a10 * a22 - a12 * a20) * inv));
        s_par[4] = tf32r((float)( (a00 * a22 - a02 * a20) * inv));
        s_par[5] = tf32r((float)(-(a00 * a12 - a02 * a10) * inv));
        s_par[6] = center[b * 3 + 0];
        s_par[7] = center[b * 3 + 1];
        s_par[8] = center[b * 3 + 2];
        s_par[9]  = cube[b * 3 + 0] * 0.5f;
        s_par[10] = cube[b * 3 + 1] * 0.5f;
        s_par[11] = cube[b * 3 + 2] * 0.5f;
    }
    for (int i = tid; i < 4096; i += NT) {
        hist[i] = g_hist[b * 4096 + i];
        g_hist[b * 4096 + i] = 0u;               // restore kA precondition
    }
    // init vert-min array for k_dist (full range, split across 64 CTAs)
    for (int i = b * NT + tid; i < NVB; i += NB * NT)
        g_vminb[i] = 0x7F800000u;
    __syncthreads();

    // ---- threshold via shfl prefix over 512 per-thread sums (contiguous) --
    {
        uint32_t c = 0;
#pragma unroll
        for (int k = 0; k < 8; k++) c += hist[tid * 8 + k];
        uint32_t p = c;
#pragma unroll
        for (int d = 1; d < 32; d <<= 1) {
            uint32_t n = __shfl_up_sync(0xFFFFFFFFu, p, d);
            if (lane >= d) p += n;
        }
        if (lane == 31) wsum[wid] = p;
        __syncthreads();
        if (wid == 0) {
            uint32_t w = (lane < 16) ? wsum[lane] : 0u;
            uint32_t q = w;
#pragma unroll
            for (int d = 1; d < 16; d <<= 1) {
                uint32_t n = __shfl_up_sync(0xFFFFFFFFu, q, d);
                if (lane >= d) q += n;
            }
            if (lane < 16) woff[lane] = q - w;
            if (lane == 15) woff[16] = q;
        }
        __syncthreads();
        uint32_t Pincl = p + woff[wid];
        uint32_t above = woff[16] - Pincl;
        uint32_t S = above + c;
        const uint32_t target = NSAMP;
        if (above < target && S >= target) {
            uint32_t cgt = above;
            for (int k = 7; k >= 0; k--) {
                uint32_t h = hist[tid * 8 + k];
                if (cgt + h >= target) {
                    s_T = (uint32_t)(tid * 8 + k);
                    s_need = target - cgt;
                    break;
                }
                cgt += h;
            }
        }
        __syncthreads();
    }
    uint32_t T = s_T;
    uint32_t need = s_need;

    const float* img = real + b * PIX;
    float4* out = g_samp + b * NSAMP;

    // ---- deterministic scan-based emit, interleaved bucket ownership ----
    uint32_t nk[8];
    uint32_t cnt = 0;
#pragma unroll
    for (int k = 0; k < 8; k++) {
        uint32_t bucket = (uint32_t)(k * NT + tid);
        uint32_t n = 0;
        if (bucket > T) {
            n = hist[bucket];
            if (n > SLOTS) n = SLOTS;
        }
        nk[k] = n;
        cnt += n;
    }
    {
        uint32_t p = cnt;
#pragma unroll
        for (int d = 1; d < 32; d <<= 1) {
            uint32_t n = __shfl_up_sync(0xFFFFFFFFu, p, d);
            if (lane >= d) p += n;
        }
        if (lane == 31) wsum[wid] = p;
        __syncthreads();
        if (wid == 0) {
            uint32_t w = (lane < 16) ? wsum[lane] : 0u;
            uint32_t q = w;
#pragma unroll
            for (int d = 1; d < 16; d <<= 1) {
                uint32_t n = __shfl_up_sync(0xFFFFFFFFu, q, d);
                if (lane >= d) q += n;
            }
            if (lane < 16) woff[lane] = q - w;
        }
        __syncthreads();
        uint32_t off = (p - cnt) + woff[wid];    // exclusive global offset
#pragma unroll
        for (int k = 0; k < 8; k++) {
            uint32_t n = nk[k];
            if (n) {
                uint32_t bucket = (uint32_t)(k * NT + tid);
                const uint32_t* bl = g_bl + (uint32_t)(b * 4096 + bucket) * SLOTS;
                for (uint32_t j = 0; j < n; j++) {
                    uint32_t e = bl[j];
                    uint32_t pp = e & 16383u;
                    out[off++] = pix_xyz4((int)pp, img[pp], s_par);
                }
            }
        }
    }

    // boundary bucket: sort desc by key, asc by index; take `need`
    if (tid == 0) {
        uint32_t n = hist[T];
        if (n > SLOTS) n = SLOTS;
        uint32_t arr[SLOTS];
        const uint32_t* bl = g_bl + (uint32_t)(b * 4096 + T) * SLOTS;
        for (uint32_t i = 0; i < n; i++) arr[i] = bl[i];
        for (uint32_t i = 1; i < n; i++) {
            uint32_t e = arr[i];
            int j = (int)i - 1;
            while (j >= 0) {
                uint32_t f = arr[j];
                bool before = ((e >> 14) > (f >> 14)) ||
                              ((e >> 14) == (f >> 14) && (e & 16383u) < (f & 16383u));
                if (before) { arr[j + 1] = f; j--; } else break;
            }
            arr[j + 1] = e;
        }
        uint32_t start = NSAMP - need;
        for (uint32_t i = 0; i < need && i < n; i++) {
            uint32_t pp = arr[i] & 16383u;
            out[start + i] = pix_xyz4((int)pp, img[pp], s_par);
        }
    }
}

// ===== K_DIST: blocks 0..255 vert pass (A); 256..383 sample pass (B);
//       per-batch tail sums vert mins; global tail writes the output =====
__global__ void __launch_bounds__(256)
k_dist(const float* __restrict__ verts, float* __restrict__ outp) {
    __shared__ ull   shbuf[4 * NPAIR];   // A: 4x128 packed samples; B: packed verts
    __shared__ float pm[256];
    __shared__ bool  isLastA, isLastG;

    int tid = threadIdx.x;

    if (blockIdx.x < 256) {
        // -------- A: per-vert min over a 256-sample chunk --------
        int blk = blockIdx.x;
        int b = blk >> 2;
        int chunk = blk & 3;
        ull* px = shbuf;         // 128
        ull* py = shbuf + 128;
        ull* pz = shbuf + 256;
        ull* pw = shbuf + 384;

        const float4* sp = g_samp + b * NSAMP + chunk * 256;
        if (tid < 128) {
            float4 f0 = sp[2 * tid];
            float4 f1 = sp[2 * tid + 1];
            px[tid] = pk2(f0.x, f1.x);
            py[tid] = pk2(f0.y, f1.y);
            pz[tid] = pk2(f0.z, f1.z);
            pw[tid] = pk2(f0.w, f1.w);
        }
        __syncthreads();

        if (tid < 195) {
            const float* vb = verts + b * NV * 3;
            ull nx[4], ny[4], nz[4];
            float hw[4];
            int vidx[4];
#pragma unroll
            for (int k = 0; k < 4; k++) {
                int v = 4 * tid + k;
                vidx[k] = v < NV ? v : NV - 1;
                float x = vb[3 * vidx[k]], y = vb[3 * vidx[k] + 1], z = vb[3 * vidx[k] + 2];
                nx[k] = pk2(-x, -x);
                ny[k] = pk2(-y, -y);
                nz[k] = pk2(-z, -z);
                hw[k] = 0.5f * (x * x + y * y + z * z);
            }
            float ml[4] = {1e30f, 1e30f, 1e30f, 1e30f};
            float mh[4] = {1e30f, 1e30f, 1e30f, 1e30f};
#pragma unroll 4
            for (int i = 0; i < 128; i++) {
                ull X = px[i], Y = py[i], Z = pz[i], W = pw[i];
#pragma unroll
                for (int k = 0; k < 4; k++) {
                    float2 d = dot3p(nx[k], X, ny[k], Y, nz[k], Z, W);
                    ml[k] = fminf(ml[k], d.x);
                    mh[k] = fminf(mh[k], d.y);
                }
            }
#pragma unroll
            for (int k = 0; k < 4; k++) {
                if (4 * tid + k < NV) {
                    float val = 2.0f * (fminf(ml[k], mh[k]) + hw[k]);  // >= 0
                    atomicMin(&g_vminb[b * NV + vidx[k]], __float_as_uint(val));
                }
            }
        }

        // ---- per-batch tail: last of the 4 A-blocks sums this batch ----
        __syncthreads();
        if (tid == 0) {
            __threadfence();
            uint32_t t = atomicAdd(&g_adone[b], 1u);
            isLastA = (t == 3u);
        }
        __syncthreads();
        if (isLastA) {
            __threadfence();   // acquire: other blocks' mins are visible
            float acc = 0.0f;
            for (int i = tid; i < NV; i += 256)
                acc += __uint_as_float(g_vminb[b * NV + i]);
            pm[tid] = acc;
            __syncthreads();
            for (int off = 128; off > 0; off >>= 1) {
                if (tid < off) pm[tid] += pm[tid + off];
                __syncthreads();
            }
            if (tid == 0) {
                g_adone[b] = 0u;               // restore for next replay
                double v = (double)pm[0];
                if (v < 0.0) v = 0.0;
                atomicAdd(&g_vacc, (ull)(v * 4294967296.0));
            }
        }
    } else {
        // -------- B: per-sample min over ALL verts, 2 samples/thread --------
        int blk = blockIdx.x - 256;
        int b = blk >> 1;
        int half = blk & 1;
        ull* vx = shbuf;               // NPAIR each
        ull* vy = shbuf + NPAIR;
        ull* vz = shbuf + 2 * NPAIR;
        ull* vw = shbuf + 3 * NPAIR;

        const float* vb = verts + b * NV * 3;
        for (int j = tid; j < NPAIR; j += 256) {
            float ax = vb[6 * j],     ay = vb[6 * j + 1], az = vb[6 * j + 2];
            float bx = vb[6 * j + 3], by = vb[6 * j + 4], bz = vb[6 * j + 5];
            vx[j] = pk2(ax, bx);
            vy[j] = pk2(ay, by);
            vz[j] = pk2(az, bz);
            vw[j] = pk2(0.5f * (ax * ax + ay * ay + az * az),
                        0.5f * (bx * bx + by * by + bz * bz));
        }
        int s0 = half * 512 + tid;
        int s1 = half * 512 + 256 + tid;
        float4 me0 = g_samp[b * NSAMP + s0];
        float4 me1 = g_samp[b * NSAMP + s1];
        __syncthreads();

        ull ax0 = pk2(-me0.x, -me0.x), ay0 = pk2(-me0.y, -me0.y), az0 = pk2(-me0.z, -me0.z);
        ull ax1 = pk2(-me1.x, -me1.x), ay1 = pk2(-me1.y, -me1.y), az1 = pk2(-me1.z, -me1.z);
        float m0a = 1e30f, m0b = 1e30f, m1a = 1e30f, m1b = 1e30f;
#pragma unroll 4
        for (int j = 0; j < NPAIR; j++) {
            ull X = vx[j], Y = vy[j], Z = vz[j], W = vw[j];
            float2 d0 = dot3p(ax0, X, ay0, Y, az0, Z, W);
            float2 d1 = dot3p(ax1, X, ay1, Y, az1, Z, W);
            m0a = fminf(m0a, d0.x); m0b = fminf(m0b, d0.y);
            m1a = fminf(m1a, d1.x); m1b = fminf(m1b, d1.y);
        }
        float sum = 2.0f * (fminf(m0a, m0b) + me0.w)
                  + 2.0f * (fminf(m1a, m1b) + me1.w);

        pm[tid] = sum;
        __syncthreads();
        for (int off = 128; off > 0; off >>= 1) {
            if (tid < off) pm[tid] += pm[tid + off];
            __syncthreads();
        }
        if (tid == 0) {
            double v = (double)pm[0];
            if (v < 0.0) v = 0.0;
            atomicAdd(&g_sacc, (ull)(v * 4294967296.0));
        }
    }

    // -------- global completion: last of all 384 blocks writes output ------
    __syncthreads();
    if (tid == 0) {
        __threadfence();
        uint32_t t = atomicAdd(&g_done, 1u);
        isLastG = (t == DGRID - 1u);
    }
    __syncthreads();
    if (isLastG && tid == 0) {
        __threadfence();
        double s = (double)g_sacc * (1.0 / 4294967296.0);
        double v = (double)g_vacc * (1.0 / 4294967296.0);
        outp[0] = (float)(s / (double)(NB * NSAMP)) +
                  (float)(v / (double)(NB * NV));
        g_sacc = 0ull;                         // restore for next replay
        g_vacc = 0ull;
        g_done = 0u;
    }
}

// ======================== launch ========================
extern "C" void kernel_launch(void* const* d_in, const int* in_sizes, int n_in,
                              void* d_out, int out_size) {
    const float* real   = (const float*)d_in[0];
    // d_in[1] synth unused, d_in[3] faces unused
    const float* verts  = (const float*)d_in[2];
    const float* center = (const float*)d_in[4];
    const float* Mmat   = (const float*)d_in[5];
    const float* cube   = (const float*)d_in[6];

    kA<<<1024, 256>>>(real);
    kC<<<NB, NT>>>(real, center, Mmat, cube);
    k_dist<<<DGRID, 256>>>(verts, (float*)d_out);
}